// round 13
// baseline (speedup 1.0000x reference)
#include <cuda_runtime.h>

// AdderConv + BatchNorm2d (training stats): x[8,32,28,28], W[64,32,3,3], pad=1.
// out[n,o,h,w] = -sum_k |x - w|, then per-channel BN (biased var, eps=1e-5).
//
// SINGLE kernel, grid (16 oc-quads, 8 n) = 128 blocks x 224 thr (all wave-1).
// Thread = 4 consecutive pixels x 4 ocs. x read via LDG from a padded,
// (x,x)-duplicated u64 global array (L1-resident; avoids the smem crossbar,
// which R11/R12 measurements showed to be the binder at ~4cyc/LDS x 3 LDS/k).
// w via 1 broadcast LDS.128 per tap. Phase structure with a 2-phase replay-safe
// ticket barrier: [pad by blocks ocq<4] -> B1 -> conv mainloop -> block stats
// -> B2 -> per-channel scale/bias -> in-register normalize -> single write.

__device__ __align__(16) unsigned long long g_xpad[8 * 32 * 30 * 32 + 64];
__device__ float g_psum[64 * 8];      // [oc][n]
__device__ float g_psumsq[64 * 8];
__device__ unsigned g_ctr;            // monotonic ticket counter (never reset)

__device__ __forceinline__ void adder2(unsigned long long& acc,
                                       unsigned long long xx,
                                       unsigned long long w,
                                       unsigned long long mask) {
    asm("{\n\t"
        ".reg .b64 t;\n\t"
        "add.rn.f32x2 t, %1, %2;\n\t"
        "and.b64 t, t, %3;\n\t"
        "add.rn.f32x2 %0, %0, t;\n\t"
        "}"
        : "+l"(acc) : "l"(xx), "l"(w), "l"(mask));
}

__device__ __forceinline__ void ticket_barrier_128() {
    // Each launch consumes 256 tickets (2 barriers x 128 blocks); formula
    // ((a>>7)+1)<<7 yields the correct release point for both phases.
    __threadfence();
    unsigned a = atomicAdd(&g_ctr, 1u);
    unsigned target = ((a >> 7) + 1u) << 7;
    while ((int)(*(volatile unsigned*)&g_ctr - target) < 0) __nanosleep(64);
    __threadfence();
}

__global__ __launch_bounds__(224) void fused_kernel(
    const float* __restrict__ x, const float* __restrict__ W,
    const float* __restrict__ gamma, const float* __restrict__ beta,
    float* __restrict__ out)
{
    __shared__ __align__(16) ulonglong2 nws[288];   // 4.6KB: {(-w0,-w1),(-w2,-w3)}/k
    __shared__ float red[8][7];                     // warp partials
    __shared__ float2 scb[4];                       // per-oc {scale, bias}

    const int ocq = blockIdx.x;   // 0..15 (ocs ocq*4 .. ocq*4+3)
    const int n   = blockIdx.y;   // 0..7
    const int tid = threadIdx.x;
    const int wid = tid >> 5;     // 0..6
    const int lid = tid & 31;
    const bool act = (lid < 28);
    int sr = lid / 7, cg = lid % 7;
    if (!act) { sr = 0; cg = 0; }                   // clamp; excluded from stats/stores
    const int row  = wid * 4 + sr;                  // 0..27
    const int col0 = cg * 4;                        // 0,4,...,24

    // ---- weights into smem (block-local) ----
    const float* Wb = W + (ocq * 4) * 288;
    unsigned long long* nw64 = (unsigned long long*)nws;
    for (int i = tid; i < 576; i += 224) {
        int k = i >> 1, pr = i & 1;
        unsigned lo = __float_as_uint(-Wb[(2 * pr) * 288 + k]);
        unsigned hi = __float_as_uint(-Wb[(2 * pr + 1) * 288 + k]);
        nw64[k * 2 + pr] = ((unsigned long long)hi << 32) | lo;
    }

    // ---- padding: blocks ocq<4 build 8 channels of padded dup-x for their n ----
    if (ocq < 4) {
        const int c0 = ocq * 8;
        const float* xb = x + ((size_t)n * 32 + c0) * 784;
        unsigned long long* dst = g_xpad + ((size_t)(n * 32 + c0)) * 960;
        for (int i = tid; i < 7680; i += 224) {
            int lc = i / 960;
            int rem = i - lc * 960;
            int h = rem >> 5, w = rem & 31;
            float v = 0.f;
            if (h >= 1 && h <= 28 && w >= 1 && w <= 28)
                v = xb[lc * 784 + (h - 1) * 28 + (w - 1)];
            unsigned u = __float_as_uint(v);
            dst[lc * 960 + h * 32 + w] = ((unsigned long long)u << 32) | u;
        }
    }
    __threadfence();
    __syncthreads();
    if (tid == 0) ticket_barrier_128();   // B1: padding complete everywhere
    __syncthreads();

    // ---- conv mainloop: 4 px x 4 oc per thread ----
    const unsigned long long mask = 0x7FFFFFFF7FFFFFFFULL;
    unsigned long long a01[4] = {0ull, 0ull, 0ull, 0ull};   // (oc0,oc1) per px
    unsigned long long a23[4] = {0ull, 0ull, 0ull, 0ull};   // (oc2,oc3) per px

    const unsigned long long* xbase =
        g_xpad + (((size_t)(n * 32)) * 30 + row) * 32 + col0;

    #pragma unroll 1
    for (int c = 0; c < 32; ++c) {
        #pragma unroll
        for (int dr = 0; dr < 3; ++dr) {
            const unsigned long long* xr = xbase + c * 960 + dr * 32;
            ulonglong2 xA = *(const ulonglong2*)(xr);       // dup q0,q1
            ulonglong2 xB = *(const ulonglong2*)(xr + 2);   // dup q2,q3
            ulonglong2 xC = *(const ulonglong2*)(xr + 4);   // dup q4,q5
            unsigned long long d[6] = {xA.x, xA.y, xB.x, xB.y, xC.x, xC.y};
            const int kb = c * 9 + dr * 3;
            #pragma unroll
            for (int dq = 0; dq < 3; ++dq) {
                ulonglong2 wv = nws[kb + dq];               // broadcast LDS.128
                adder2(a01[0], d[dq],     wv.x, mask);
                adder2(a23[0], d[dq],     wv.y, mask);
                adder2(a01[1], d[dq + 1], wv.x, mask);
                adder2(a23[1], d[dq + 1], wv.y, mask);
                adder2(a01[2], d[dq + 2], wv.x, mask);
                adder2(a23[2], d[dq + 2], wv.y, mask);
                adder2(a01[3], d[dq + 3], wv.x, mask);
                adder2(a23[3], d[dq + 3], wv.y, mask);
            }
        }
    }

    // ---- unpack 16 positive abs-sums: val[px][oc] ----
    float val[4][4];
    #pragma unroll
    for (int p = 0; p < 4; ++p) {
        val[p][0] = __uint_as_float((unsigned)(a01[p] & 0xFFFFFFFFu));
        val[p][1] = __uint_as_float((unsigned)(a01[p] >> 32));
        val[p][2] = __uint_as_float((unsigned)(a23[p] & 0xFFFFFFFFu));
        val[p][3] = __uint_as_float((unsigned)(a23[p] >> 32));
    }

    // ---- block stats: this block covers the FULL image for its 4 ocs ----
    float sv[4], qv[4];
    #pragma unroll
    for (int j = 0; j < 4; ++j) {
        float s = 0.f, q = 0.f;
        #pragma unroll
        for (int p = 0; p < 4; ++p) {
            float v = val[p][j];
            s -= v;              // out value is -val
            q += v * v;
        }
        sv[j] = act ? s : 0.f;
        qv[j] = act ? q : 0.f;
    }
    #pragma unroll
    for (int dd = 16; dd > 0; dd >>= 1) {
        #pragma unroll
        for (int j = 0; j < 4; ++j) {
            sv[j] += __shfl_down_sync(0xFFFFFFFFu, sv[j], dd);
            qv[j] += __shfl_down_sync(0xFFFFFFFFu, qv[j], dd);
        }
    }
    if (lid == 0) {
        #pragma unroll
        for (int j = 0; j < 4; ++j) {
            red[j][wid]     = sv[j];
            red[4 + j][wid] = qv[j];
        }
    }
    __syncthreads();
    if (tid < 8) {
        float t = red[tid][0];
        #pragma unroll
        for (int u = 1; u < 7; ++u) t += red[tid][u];
        if (tid < 4) g_psum[(ocq * 4 + tid) * 8 + n] = t;
        else         g_psumsq[(ocq * 4 + (tid - 4)) * 8 + n] = t;
    }
    __threadfence();
    __syncthreads();
    if (tid == 0) ticket_barrier_128();   // B2: all (n,oc) stats published
    __syncthreads();

    // ---- per-channel scale/bias: 32 threads fold the 8 batch partials ----
    if (tid < 32) {
        const int j = tid >> 3, nn = tid & 7;
        const int oc = ocq * 4 + j;
        float ss = *(volatile float*)&g_psum[oc * 8 + nn];
        float qq = *(volatile float*)&g_psumsq[oc * 8 + nn];
        #pragma unroll
        for (int dd = 4; dd > 0; dd >>= 1) {
            ss += __shfl_down_sync(0xFFFFFFFFu, ss, dd, 8);
            qq += __shfl_down_sync(0xFFFFFFFFu, qq, dd, 8);
        }
        if (nn == 0) {
            float mean = ss * (1.f / 6272.f);
            float var  = qq * (1.f / 6272.f) - mean * mean;
            float sc = gamma[oc] * rsqrtf(var + 1e-5f);
            scb[j] = make_float2(sc, beta[oc] - mean * sc);
        }
    }
    __syncthreads();

    // ---- normalize in registers, write 4 px per oc (float2 pairs, 8B-aligned) ----
    if (act) {
        #pragma unroll
        for (int j = 0; j < 4; ++j) {
            float2 cb = scb[j];
            float* ob = out + ((size_t)(n * 64 + ocq * 4 + j)) * 784 + row * 28 + col0;
            // y = (-val)*sc + bi
            *(float2*)(ob)     = make_float2(fmaf(val[0][j], -cb.x, cb.y),
                                             fmaf(val[1][j], -cb.x, cb.y));
            *(float2*)(ob + 2) = make_float2(fmaf(val[2][j], -cb.x, cb.y),
                                             fmaf(val[3][j], -cb.x, cb.y));
        }
    }
}

extern "C" void kernel_launch(void* const* d_in, const int* in_sizes, int n_in,
                              void* d_out, int out_size) {
    const float* x     = (const float*)d_in[0];  // [8,32,28,28]
    const float* W     = (const float*)d_in[1];  // [64,32,3,3]
    const float* gamma = (const float*)d_in[2];  // [64]
    const float* beta  = (const float*)d_in[3];  // [64]
    float* out = (float*)d_out;                  // [8,64,28,28]

    dim3 g1(16, 8);
    fused_kernel<<<g1, 224>>>(x, W, gamma, beta, out);
}